// round 9
// baseline (speedup 1.0000x reference)
#include <cuda_runtime.h>
#include <math.h>

#define B_  32
#define G_  50
#define NC_ 80
#define NA_ 8400
#define BNA_ (B_*NA_)

// ---------------- device scratch ----------------
__device__ float4        g_box [BNA_];
__device__ float         g_obj [BNA_];
__device__ float         g_Bo  [BNA_];
__device__ int           g_flist[BNA_];
__device__ int           g_nfg [B_];
// compacted per-fg-anchor data (index f)
__device__ float4        g_cbox[BNA_];          // decoded box
__device__ float4        g_cgeo[BNA_];          // cx, cy, rs, s
__device__ float         g_csp [BNA_];          // sum softplus(x_c)
__device__ float         g_cobj[BNA_];          // obj logit
__device__ float         g_U   [NC_*BNA_];      // slot planes: log((1-pv)/pv)
__device__ int           g_slotofcls[B_*NC_];   // class -> slot (-1 unused)
__device__ float         g_cost[B_*G_*NA_];
__device__ float         g_ioum[B_*G_*NA_];
__device__ float         g_gtbox[B_*G_*4];
__device__ int           g_gtcls[B_*G_];
__device__ unsigned char g_gtval[B_*G_];
__device__ float         g_thr [B_*G_];
__device__ double        g_accb[B_][4];

__device__ __forceinline__ void anchor_map(int a, int& hw, int& W, int& HW, float& st) {
    if (a < 6400)      { hw = a;        W = 80; HW = 6400; st = 8.f;  }
    else if (a < 8000) { hw = a - 6400; W = 40; HW = 1600; st = 16.f; }
    else               { hw = a - 8000; W = 20; HW = 400;  st = 32.f; }
}

// register-resident sorted lists (static indexing, branchless bubble)
__device__ __forceinline__ void ins_min10(float (&t)[10], float c) {
    if (c < t[9]) {
        t[9] = c;
        #pragma unroll
        for (int j = 9; j > 0; j--) {
            float lo = fminf(t[j-1], t[j]);
            float hi = fmaxf(t[j-1], t[j]);
            t[j-1] = lo; t[j] = hi;
        }
    }
}
__device__ __forceinline__ void ins_max10(float (&t)[10], float c) {
    if (c > t[9]) {
        t[9] = c;
        #pragma unroll
        for (int j = 9; j > 0; j--) {
            float hi = fmaxf(t[j-1], t[j]);
            float lo = fminf(t[j-1], t[j]);
            t[j-1] = hi; t[j] = lo;
        }
    }
}

// ---------------- K1: gt extraction + zero + class slot map (block per batch) ----------------
__global__ void k_gt(const float* __restrict__ labels) {
    int b = blockIdx.x;
    int tid = threadIdx.x;
    __shared__ unsigned um[3];
    if (tid < 3) um[tid] = 0u;
    if (tid < 4) g_accb[b][tid] = 0.0;
    if (tid == 0) g_nfg[b] = 0;
    __syncthreads();

    if (tid < G_) {
        int i = b * G_ + tid;
        const float* l = labels + i * 5;
        float c = l[0], x = l[1], y = l[2], w = l[3], h = l[4];
        bool val = (c + x + y + w + h) > 0.f;
        g_gtval[i] = val;
        g_gtbox[i*4+0] = x; g_gtbox[i*4+1] = y; g_gtbox[i*4+2] = w; g_gtbox[i*4+3] = h;
        int ci = (int)c;
        g_gtcls[i] = ci;
        if (val) atomicOr(&um[ci >> 5], 1u << (ci & 31));
    }
    __syncthreads();

    if (tid < NC_) {
        unsigned m0 = um[0], m1 = um[1], m2 = um[2];
        bool used = (tid < 32) ? ((m0 >> tid) & 1u)
                  : (tid < 64) ? ((m1 >> (tid - 32)) & 1u)
                               : ((m2 >> (tid - 64)) & 1u);
        int slot = -1;
        if (used) {
            int cnt;
            if (tid < 32) {
                cnt = __popc(m0 & ((tid == 0) ? 0u : ((1u << tid) - 1u)));
            } else if (tid < 64) {
                int t = tid - 32;
                cnt = __popc(m0) + __popc(m1 & ((t == 0) ? 0u : ((1u << t) - 1u)));
            } else {
                int t = tid - 64;
                cnt = __popc(m0) + __popc(m1) + __popc(m2 & ((t == 0) ? 0u : ((1u << t) - 1u)));
            }
            slot = cnt;
        }
        g_slotofcls[b * NC_ + tid] = slot;
    }
}

// ---------------- K2: decode + fg + compact + obj softplus ----------------
__global__ void k_decode(const float* __restrict__ out0,
                         const float* __restrict__ out1,
                         const float* __restrict__ out2) {
    __shared__ float sgt[G_*4];
    __shared__ unsigned char sval[G_];
    int b = blockIdx.y;
    if (threadIdx.x < G_*4) sgt[threadIdx.x] = g_gtbox[b*G_*4 + threadIdx.x];
    if (threadIdx.x < G_)   sval[threadIdx.x] = g_gtval[b*G_ + threadIdx.x];
    __syncthreads();

    int a = blockIdx.x * blockDim.x + threadIdx.x;
    int lane = threadIdx.x & 31;
    float softplus_obj = 0.f;
    bool fg = false;

    if (a < NA_) {
        int idx = b * NA_ + a;
        int hw, W, HW; float st;
        anchor_map(a, hw, W, HW, st);
        const float* src = (a < 6400) ? out0 : (a < 8000) ? out1 : out2;
        const float* p = src + (size_t)b * 85 * HW + hw;

        float tx = p[0], ty = p[HW], tw = p[2*HW], th = p[3*HW], to = p[4*HW];
        int h = hw / W, w = hw - h * W;
        g_box[idx] = make_float4((tx + (float)w) * st, (ty + (float)h) * st,
                                 __expf(tw) * st, __expf(th) * st);
        g_obj[idx] = to;
        g_Bo[idx] = 1.f + __expf(-to);
        softplus_obj = fmaxf(to, 0.f) + __logf(1.f + __expf(-fabsf(to)));

        float cx = ((float)w + 0.5f) * st, cy = ((float)h + 0.5f) * st;
        float rs = 2.5f * st;
        for (int g = 0; g < G_; g++) {
            if (!sval[g]) continue;
            float gx = sgt[g*4], gy = sgt[g*4+1], gw = sgt[g*4+2], gh = sgt[g*4+3];
            bool ib = (cx > gx - 0.5f*gw) && (cx < gx + 0.5f*gw) &&
                      (cy > gy - 0.5f*gh) && (cy < gy + 0.5f*gh);
            bool ic = (fabsf(cx - gx) < rs) && (fabsf(cy - gy) < rs);
            fg |= (ib | ic);
        }
    }

    // warp-aggregated compaction append
    unsigned bal = __ballot_sync(0xffffffffu, fg);
    if (bal) {
        int leader = __ffs(bal) - 1;
        int base = 0;
        if (lane == leader) base = atomicAdd(&g_nfg[b], __popc(bal));
        base = __shfl_sync(0xffffffffu, base, leader);
        if (fg) g_flist[b*NA_ + base + __popc(bal & ((1u << lane) - 1))] = a;
    }

    #pragma unroll
    for (int off = 16; off; off >>= 1)
        softplus_obj += __shfl_down_sync(0xffffffffu, softplus_obj, off);
    __shared__ float swsum[8];
    int wid = threadIdx.x >> 5;
    if (lane == 0) swsum[wid] = softplus_obj;
    __syncthreads();
    if (threadIdx.x == 0) {
        float t = 0.f;
        for (int i = 0; i < 8; i++) t += swsum[i];
        atomicAdd(&g_accb[b][1], (double)t);
    }
}

// ---------------- K3: dense per-fg-anchor stats + compact staging ----------------
__global__ void k_stats(const float* __restrict__ out0,
                        const float* __restrict__ out1,
                        const float* __restrict__ out2) {
    __shared__ int sslot[NC_];
    int b = blockIdx.y;
    if (threadIdx.x < NC_) sslot[threadIdx.x] = g_slotofcls[b * NC_ + threadIdx.x];
    __syncthreads();

    int f = blockIdx.x * blockDim.x + threadIdx.x;
    if (f >= g_nfg[b]) return;
    int a = g_flist[b*NA_ + f];
    int idx = b * NA_ + a;
    int hw, W, HW; float st;
    anchor_map(a, hw, W, HW, st);
    const float* src = (a < 6400) ? out0 : (a < 8000) ? out1 : out2;
    const float* p = src + ((size_t)b * 85 + 5) * HW + hw;
    float Bo = g_Bo[idx];
    int bf = b * NA_ + f;

    float s = 0.f, splog = 0.f, xsum = 0.f;
    #pragma unroll 2
    for (int c = 0; c < NC_; c += 4) {
        float x0 = __ldg(&p[(c+0)*HW]);
        float x1 = __ldg(&p[(c+1)*HW]);
        float x2 = __ldg(&p[(c+2)*HW]);
        float x3 = __ldg(&p[(c+3)*HW]);
        float A0 = 1.f + __expf(-x0);
        float A1 = 1.f + __expf(-x1);
        float A2 = 1.f + __expf(-x2);
        float A3 = 1.f + __expf(-x3);
        float pv0 = fminf(fmaxf(rsqrtf(A0*Bo), 1e-7f), 1.f - 1e-6f);
        float pv1 = fminf(fmaxf(rsqrtf(A1*Bo), 1e-7f), 1.f - 1e-6f);
        float pv2 = fminf(fmaxf(rsqrtf(A2*Bo), 1e-7f), 1.f - 1e-6f);
        float pv3 = fminf(fmaxf(rsqrtf(A3*Bo), 1e-7f), 1.f - 1e-6f);
        s     += __logf(((1.f-pv0)*(1.f-pv1)) * ((1.f-pv2)*(1.f-pv3)));
        splog += __logf((A0*A1) * (A2*A3));
        xsum  += (x0 + x1) + (x2 + x3);
        // slot planes only for classes used by some valid gt (uniform branch per block)
        int s0_ = sslot[c+0], s1_ = sslot[c+1], s2_ = sslot[c+2], s3_ = sslot[c+3];
        if (s0_ >= 0) g_U[(size_t)s0_*BNA_ + bf] = __logf((1.f-pv0)/pv0);
        if (s1_ >= 0) g_U[(size_t)s1_*BNA_ + bf] = __logf((1.f-pv1)/pv1);
        if (s2_ >= 0) g_U[(size_t)s2_*BNA_ + bf] = __logf((1.f-pv2)/pv2);
        if (s3_ >= 0) g_U[(size_t)s3_*BNA_ + bf] = __logf((1.f-pv3)/pv3);
    }
    g_csp [bf] = xsum + splog;      // sum softplus(x_c)
    g_cobj[bf] = g_obj[idx];
    g_cbox[bf] = g_box[idx];
    int h = hw / W, w = hw - h * W;
    g_cgeo[bf] = make_float4(((float)w + 0.5f) * st, ((float)h + 0.5f) * st,
                             2.5f * st, s);
}

// ---------------- K4: fused cost + topk, WARP per (b,g) row ----------------
#define CW_ 8
__global__ void k_costtopk() {
    int b = blockIdx.y;
    int wid = threadIdx.x >> 5, lane = threadIdx.x & 31;
    int g = blockIdx.x * CW_ + wid;
    if (g >= G_) return;
    int gi = b * G_ + g;
    if (!g_gtval[gi]) return;
    int N = g_nfg[b];
    if (N == 0) return;

    float gx = g_gtbox[gi*4+0], gy = g_gtbox[gi*4+1];
    float gw = g_gtbox[gi*4+2], gh = g_gtbox[gi*4+3];
    int   slot = g_slotofcls[b * NC_ + g_gtcls[gi]];
    float gl = gx - gw*0.5f, gr = gx + gw*0.5f;
    float gt_ = gy - gh*0.5f, gbm = gy + gh*0.5f;
    float areag = gw * gh;
    int row = gi * NA_;
    const float*  Up   = g_U + (size_t)slot * BNA_ + b * NA_;
    const float4* cbox = g_cbox + b * NA_;
    const float4* cgeo = g_cgeo + b * NA_;

    float lc[10], li[10];
    #pragma unroll
    for (int i = 0; i < 10; i++) { lc[i] = 3.0e38f; li[i] = 0.f; }

    for (int f = lane; f < N; f += 32) {
        float4 bb = cbox[f];
        float4 ge = cgeo[f];
        float  U  = Up[f];

        float bz2 = bb.z * 0.5f, bw2 = bb.w * 0.5f;
        float tlx = fmaxf(gl,  bb.x - bz2);
        float tly = fmaxf(gt_, bb.y - bw2);
        float brx = fminf(gr,  bb.x + bz2);
        float bry = fminf(gbm, bb.y + bw2);
        float en  = (tlx < brx && tly < bry) ? 1.f : 0.f;
        float inter = (brx - tlx) * (bry - tly) * en;
        float iou = inter / (areag + bb.z*bb.w - inter + 1e-12f);

        bool ib = (ge.x > gl) && (ge.x < gr) && (ge.y > gt_) && (ge.y < gbm);
        bool ic = (fabsf(ge.x - gx) < ge.z) && (fabsf(ge.y - gy) < ge.z);
        bool geom = ib && ic;

        float t = iou + 1e-8f;
        float cost = U - ge.w - 3.f * __logf(t) + (geom ? 0.f : 100000.f);

        g_cost[row + f] = cost;
        g_ioum[row + f] = iou;
        ins_min10(lc, cost);
        ins_max10(li, iou);
    }

    // direct 32-lane shuffle merge (no shared, no block sync)
    float isum = 0.f;
    for (int k = 0; k < 10; k++) {
        float bv = li[0]; int bl = lane;
        #pragma unroll
        for (int off = 16; off; off >>= 1) {
            float ov = __shfl_down_sync(0xffffffffu, bv, off);
            int   ol = __shfl_down_sync(0xffffffffu, bl, off);
            if (ov > bv || (ov == bv && ol < bl)) { bv = ov; bl = ol; }
        }
        bv = __shfl_sync(0xffffffffu, bv, 0);
        bl = __shfl_sync(0xffffffffu, bl, 0);
        if (lane == bl) {
            #pragma unroll
            for (int j = 0; j < 9; j++) li[j] = li[j+1];
            li[9] = -3.0e38f;
        }
        isum += bv;
    }
    int dynk = (int)isum;
    if (dynk < 1) dynk = 1;
    if (dynk > 10) dynk = 10;
    if (dynk > N) dynk = N;

    float thr = 0.f;
    for (int k = 0; k < 10; k++) {
        float bv = lc[0]; int bl = lane;
        #pragma unroll
        for (int off = 16; off; off >>= 1) {
            float ov = __shfl_down_sync(0xffffffffu, bv, off);
            int   ol = __shfl_down_sync(0xffffffffu, bl, off);
            if (ov < bv || (ov == bv && ol < bl)) { bv = ov; bl = ol; }
        }
        bv = __shfl_sync(0xffffffffu, bv, 0);
        bl = __shfl_sync(0xffffffffu, bl, 0);
        if (lane == bl) {
            #pragma unroll
            for (int j = 0; j < 9; j++) lc[j] = lc[j+1];
            lc[9] = 3.0e38f;
        }
        if (k == dynk - 1) thr = bv;
    }
    if (lane == 0) g_thr[gi] = thr;
}

// ---------------- K5: resolve (warp per fg anchor) + losses ----------------
#define RW_ 8
__global__ void k_resolve(const float* __restrict__ out0,
                          const float* __restrict__ out1,
                          const float* __restrict__ out2) {
    int b = blockIdx.y;
    int wid = threadIdx.x >> 5, lane = threadIdx.x & 31;
    int f = blockIdx.x * RW_ + wid;
    int nfg = g_nfg[b];
    bool active = (f < nfg);

    float liou = 0.f, lobj = 0.f, lcls = 0.f, lfg = 0.f;

    if (active) {
        int bf = b * NA_ + f;

        int g0 = lane, g1 = lane + 32;
        bool v0 = g_gtval[b*G_ + g0];
        bool v1 = (g1 < G_) ? (g_gtval[b*G_ + g1] != 0) : false;
        float c0 = v0 ? __ldg(&g_cost[(b*G_ + g0) * NA_ + f]) : 3.4e38f;
        float c1 = v1 ? __ldg(&g_cost[(b*G_ + g1) * NA_ + f]) : 3.4e38f;
        float t0 = v0 ? g_thr[b*G_ + g0] : 0.f;
        float t1 = v1 ? g_thr[b*G_ + g1] : 0.f;
        bool m0 = v0 && (c0 <= t0);
        bool m1 = v1 && (c1 <= t1);
        int count = __popc(__ballot_sync(0xffffffffu, m0))
                  + __popc(__ballot_sync(0xffffffffu, m1));

        float cmin = fminf(c0, c1);
        int   gmin = (c0 <= c1) ? g0 : g1;
        #pragma unroll
        for (int off = 16; off; off >>= 1) {
            float ov = __shfl_xor_sync(0xffffffffu, cmin, off);
            int   og = __shfl_xor_sync(0xffffffffu, gmin, off);
            if (ov < cmin || (ov == cmin && og < gmin)) { cmin = ov; gmin = og; }
        }

        if (count > 1) {
            m0 = m0 && (g0 == gmin);
            m1 = m1 && (g1 == gmin);
        }
        unsigned fb0 = __ballot_sync(0xffffffffu, m0);
        unsigned fb1 = __ballot_sync(0xffffffffu, m1);
        bool fgfin = (fb0 | fb1) != 0u;

        if (fgfin) {
            int mg = fb0 ? (__ffs(fb0) - 1) : (32 + __ffs(fb1) - 1);

            float io = 0.f;
            if (m0) io += __ldg(&g_ioum[(b*G_ + g0) * NA_ + f]);
            if (m1) io += __ldg(&g_ioum[(b*G_ + g1) * NA_ + f]);
            #pragma unroll
            for (int off = 16; off; off >>= 1)
                io += __shfl_xor_sync(0xffffffffu, io, off);
            float piou = io;

            if (lane == (mg & 31)) {
                int gi = b * G_ + mg;
                float4 bb = g_cbox[bf];
                float gx = g_gtbox[gi*4+0], gy = g_gtbox[gi*4+1];
                float gw = g_gtbox[gi*4+2], gh = g_gtbox[gi*4+3];
                float tlx = fmaxf(bb.x - bb.z*0.5f, gx - gw*0.5f);
                float tly = fmaxf(bb.y - bb.w*0.5f, gy - gh*0.5f);
                float brx = fminf(bb.x + bb.z*0.5f, gx + gw*0.5f);
                float bry = fminf(bb.y + bb.w*0.5f, gy + gh*0.5f);
                float en  = (tlx < brx && tly < bry) ? 1.f : 0.f;
                float inter = fmaxf(brx - tlx, 0.f) * fmaxf(bry - tly, 0.f) * en;
                float uni = bb.z*bb.w + gw*gh - inter + 1e-16f;
                float iou = inter / uni;
                liou = 1.f - iou * iou;
                lfg  = 1.f;
                lobj = -g_cobj[bf];

                int mcls = g_gtcls[gi];
                int a = g_flist[b*NA_ + f];
                int hw, W, HW; float st;
                anchor_map(a, hw, W, HW, st);
                const float* src = (a < 6400) ? out0 : (a < 8000) ? out1 : out2;
                float xm = __ldg(&src[((size_t)b * 85 + 5 + mcls) * HW + hw]);
                lcls = g_csp[bf] - xm * piou;
            }
        }
    }

    #pragma unroll
    for (int off = 16; off; off >>= 1) {
        liou += __shfl_down_sync(0xffffffffu, liou, off);
        lobj += __shfl_down_sync(0xffffffffu, lobj, off);
        lcls += __shfl_down_sync(0xffffffffu, lcls, off);
        lfg  += __shfl_down_sync(0xffffffffu, lfg,  off);
    }
    __shared__ float s4[RW_][4];
    if (lane == 0) { s4[wid][0] = liou; s4[wid][1] = lobj; s4[wid][2] = lcls; s4[wid][3] = lfg; }
    __syncthreads();
    if (threadIdx.x == 0) {
        float a0 = 0.f, a1 = 0.f, a2 = 0.f, a3 = 0.f;
        for (int i = 0; i < RW_; i++) { a0 += s4[i][0]; a1 += s4[i][1]; a2 += s4[i][2]; a3 += s4[i][3]; }
        if (a0 != 0.f) atomicAdd(&g_accb[b][0], (double)a0);
        if (a1 != 0.f) atomicAdd(&g_accb[b][1], (double)a1);
        if (a2 != 0.f) atomicAdd(&g_accb[b][2], (double)a2);
        if (a3 != 0.f) atomicAdd(&g_accb[b][3], (double)a3);
    }
}

// ---------------- K6: finalize ----------------
__global__ void k_final(float* __restrict__ out) {
    if (threadIdx.x == 0) {
        double si = 0.0, so = 0.0, sc = 0.0, nf = 0.0;
        for (int b = 0; b < B_; b++) {
            si += g_accb[b][0]; so += g_accb[b][1];
            sc += g_accb[b][2]; nf += g_accb[b][3];
        }
        if (nf < 1.0) nf = 1.0;
        out[0] = (float)((5.0 * si + so + sc) / nf);
    }
}

// ---------------- launch ----------------
extern "C" void kernel_launch(void* const* d_in, const int* in_sizes, int n_in,
                              void* d_out, int out_size) {
    const float* out0   = (const float*)d_in[0];
    const float* out1   = (const float*)d_in[1];
    const float* out2   = (const float*)d_in[2];
    const float* labels = (const float*)d_in[3];
    float* out = (float*)d_out;

    k_gt<<<B_, 128>>>(labels);
    {
        dim3 g((NA_ + 255) / 256, B_);
        k_decode<<<g, 256>>>(out0, out1, out2);
    }
    {
        dim3 g((NA_ + 255) / 256, B_);
        k_stats<<<g, 256>>>(out0, out1, out2);
    }
    {
        dim3 g((G_ + CW_ - 1) / CW_, B_);
        k_costtopk<<<g, CW_*32>>>();
    }
    {
        dim3 g((NA_ + RW_ - 1) / RW_, B_);
        k_resolve<<<g, 256>>>(out0, out1, out2);
    }
    k_final<<<1, 32>>>(out);
}

// round 11
// speedup vs baseline: 1.3279x; 1.3279x over previous
#include <cuda_runtime.h>
#include <math.h>

#define B_  32
#define G_  50
#define NC_ 80
#define NA_ 8400
#define BNA_ (B_*NA_)

// ---------------- device scratch ----------------
__device__ int           g_flist[BNA_];
__device__ int           g_nfg [B_];
// compacted per-fg-anchor data (index f), written by decode/stats
__device__ float4        g_cbox[BNA_];          // decoded box
__device__ float4        g_cgeo[BNA_];          // cx, cy, rs, s(from stats)
__device__ float         g_cBo [BNA_];          // 1+exp(-obj)
__device__ float         g_csp [BNA_];          // sum softplus(x_c)
__device__ float         g_cobj[BNA_];          // obj logit
__device__ float         g_U   [G_*BNA_];       // slot planes: log((1-pv)/pv)
__device__ int           g_slotofcls[B_*NC_];   // class -> slot (-1 unused)
// compacted valid gts (index j, order-preserving)
__device__ float4        g_vgtbox[B_*G_];
__device__ int           g_vgtcls[B_*G_];
__device__ int           g_nval [B_];
// cost/iou interleaved, [b][f][j] layout (coalesced for resolve)
__device__ float2        g_ci[(size_t)BNA_*G_];
__device__ float         g_thr [B_*G_];
__device__ double        g_accb[B_][4];

__device__ __forceinline__ void anchor_map(int a, int& hw, int& W, int& HW, float& st) {
    if (a < 6400)      { hw = a;        W = 80; HW = 6400; st = 8.f;  }
    else if (a < 8000) { hw = a - 6400; W = 40; HW = 1600; st = 16.f; }
    else               { hw = a - 8000; W = 20; HW = 400;  st = 32.f; }
}

// register-resident sorted lists (static indexing, branchless bubble)
__device__ __forceinline__ void ins_min10(float (&t)[10], float c) {
    if (c < t[9]) {
        t[9] = c;
        #pragma unroll
        for (int j = 9; j > 0; j--) {
            float lo = fminf(t[j-1], t[j]);
            float hi = fmaxf(t[j-1], t[j]);
            t[j-1] = lo; t[j] = hi;
        }
    }
}
__device__ __forceinline__ void ins_max10(float (&t)[10], float c) {
    if (c > t[9]) {
        t[9] = c;
        #pragma unroll
        for (int j = 9; j > 0; j--) {
            float hi = fmaxf(t[j-1], t[j]);
            float lo = fminf(t[j-1], t[j]);
            t[j-1] = hi; t[j] = lo;
        }
    }
}

// ---------------- K1: gts + zero + valid compaction + class slot map ----------------
__global__ void k_gt(const float* __restrict__ labels) {
    int b = blockIdx.x;
    int tid = threadIdx.x;
    __shared__ unsigned um[3];
    __shared__ float4 sbox[G_];
    __shared__ int scls[G_];
    __shared__ unsigned char sv[G_];
    if (tid < 3) um[tid] = 0u;
    if (tid < 4) g_accb[b][tid] = 0.0;
    if (tid == 0) g_nfg[b] = 0;
    __syncthreads();

    if (tid < G_) {
        const float* l = labels + (b * G_ + tid) * 5;
        float c = l[0], x = l[1], y = l[2], w = l[3], h = l[4];
        bool val = (c + x + y + w + h) > 0.f;
        sv[tid] = val;
        sbox[tid] = make_float4(x, y, w, h);
        int ci = (int)c;
        scls[tid] = ci;
        if (val) atomicOr(&um[ci >> 5], 1u << (ci & 31));
    }
    __syncthreads();

    if (tid == 0) {
        int cnt = 0;
        for (int g = 0; g < G_; g++) {
            if (sv[g]) {
                g_vgtbox[b*G_ + cnt] = sbox[g];
                g_vgtcls[b*G_ + cnt] = scls[g];
                cnt++;
            }
        }
        g_nval[b] = cnt;
    }

    if (tid < NC_) {
        unsigned m0 = um[0], m1 = um[1], m2 = um[2];
        bool used = (tid < 32) ? ((m0 >> tid) & 1u)
                  : (tid < 64) ? ((m1 >> (tid - 32)) & 1u)
                               : ((m2 >> (tid - 64)) & 1u);
        int slot = -1;
        if (used) {
            int cnt;
            if (tid < 32) {
                cnt = __popc(m0 & ((tid == 0) ? 0u : ((1u << tid) - 1u)));
            } else if (tid < 64) {
                int t = tid - 32;
                cnt = __popc(m0) + __popc(m1 & ((t == 0) ? 0u : ((1u << t) - 1u)));
            } else {
                int t = tid - 64;
                cnt = __popc(m0) + __popc(m1) + __popc(m2 & ((t == 0) ? 0u : ((1u << t) - 1u)));
            }
            slot = cnt;
        }
        g_slotofcls[b * NC_ + tid] = slot;
    }
}

// ---------------- K2: decode + fg + compact staging + obj softplus ----------------
__global__ void k_decode(const float* __restrict__ out0,
                         const float* __restrict__ out1,
                         const float* __restrict__ out2) {
    __shared__ float4 svb[G_];
    __shared__ int snv;
    int b = blockIdx.y;
    if (threadIdx.x == 0) snv = g_nval[b];
    if (threadIdx.x < G_) svb[threadIdx.x] = g_vgtbox[b*G_ + threadIdx.x];
    __syncthreads();
    int nv = snv;

    int a = blockIdx.x * blockDim.x + threadIdx.x;
    int lane = threadIdx.x & 31;
    float softplus_obj = 0.f;
    bool fg = false;
    float4 box = make_float4(0.f, 0.f, 0.f, 0.f);
    float Bo = 0.f, to = 0.f, cx = 0.f, cy = 0.f, rs = 0.f;

    if (a < NA_) {
        int hw, W, HW; float st;
        anchor_map(a, hw, W, HW, st);
        const float* src = (a < 6400) ? out0 : (a < 8000) ? out1 : out2;
        const float* p = src + (size_t)b * 85 * HW + hw;

        float tx = p[0], ty = p[HW], tw = p[2*HW], th = p[3*HW];
        to = p[4*HW];
        int h = hw / W, w = hw - h * W;
        box = make_float4((tx + (float)w) * st, (ty + (float)h) * st,
                          __expf(tw) * st, __expf(th) * st);
        Bo = 1.f + __expf(-to);
        softplus_obj = fmaxf(to, 0.f) + __logf(1.f + __expf(-fabsf(to)));

        cx = ((float)w + 0.5f) * st;
        cy = ((float)h + 0.5f) * st;
        rs = 2.5f * st;
        for (int j = 0; j < nv; j++) {
            float4 gb = svb[j];
            bool ib = (cx > gb.x - 0.5f*gb.z) && (cx < gb.x + 0.5f*gb.z) &&
                      (cy > gb.y - 0.5f*gb.w) && (cy < gb.y + 0.5f*gb.w);
            bool ic = (fabsf(cx - gb.x) < rs) && (fabsf(cy - gb.y) < rs);
            fg |= (ib | ic);
        }
    }

    // warp-aggregated compaction append + compacted stores
    unsigned bal = __ballot_sync(0xffffffffu, fg);
    if (bal) {
        int leader = __ffs(bal) - 1;
        int base = 0;
        if (lane == leader) base = atomicAdd(&g_nfg[b], __popc(bal));
        base = __shfl_sync(0xffffffffu, base, leader);
        if (fg) {
            int f = base + __popc(bal & ((1u << lane) - 1));
            int bf = b * NA_ + f;
            g_flist[bf] = a;
            g_cbox[bf] = box;
            g_cgeo[bf] = make_float4(cx, cy, rs, 0.f);
            g_cBo [bf] = Bo;
            g_cobj[bf] = to;
        }
    }

    #pragma unroll
    for (int off = 16; off; off >>= 1)
        softplus_obj += __shfl_down_sync(0xffffffffu, softplus_obj, off);
    __shared__ float swsum[8];
    int wid = threadIdx.x >> 5;
    if (lane == 0) swsum[wid] = softplus_obj;
    __syncthreads();
    if (threadIdx.x == 0) {
        float t = 0.f;
        for (int i = 0; i < 8; i++) t += swsum[i];
        atomicAdd(&g_accb[b][1], (double)t);
    }
}

// ---------------- K3: dense per-fg-anchor stats (slot-compressed U planes) ----------------
__global__ void k_stats(const float* __restrict__ out0,
                        const float* __restrict__ out1,
                        const float* __restrict__ out2) {
    __shared__ int sslot[NC_];
    int b = blockIdx.y;
    if (threadIdx.x < NC_) sslot[threadIdx.x] = g_slotofcls[b * NC_ + threadIdx.x];
    __syncthreads();

    int f = blockIdx.x * blockDim.x + threadIdx.x;
    if (f >= g_nfg[b]) return;
    int bf = b * NA_ + f;
    int a = g_flist[bf];
    int hw, W, HW; float st;
    anchor_map(a, hw, W, HW, st);
    const float* src = (a < 6400) ? out0 : (a < 8000) ? out1 : out2;
    const float* p = src + ((size_t)b * 85 + 5) * HW + hw;
    float Bo = g_cBo[bf];

    float s = 0.f, splog = 0.f, xsum = 0.f;
    #pragma unroll 2
    for (int c = 0; c < NC_; c += 4) {
        float x0 = __ldg(&p[(c+0)*HW]);
        float x1 = __ldg(&p[(c+1)*HW]);
        float x2 = __ldg(&p[(c+2)*HW]);
        float x3 = __ldg(&p[(c+3)*HW]);
        float A0 = 1.f + __expf(-x0);
        float A1 = 1.f + __expf(-x1);
        float A2 = 1.f + __expf(-x2);
        float A3 = 1.f + __expf(-x3);
        float pv0 = fminf(fmaxf(rsqrtf(A0*Bo), 1e-7f), 1.f - 1e-6f);
        float pv1 = fminf(fmaxf(rsqrtf(A1*Bo), 1e-7f), 1.f - 1e-6f);
        float pv2 = fminf(fmaxf(rsqrtf(A2*Bo), 1e-7f), 1.f - 1e-6f);
        float pv3 = fminf(fmaxf(rsqrtf(A3*Bo), 1e-7f), 1.f - 1e-6f);
        s     += __logf(((1.f-pv0)*(1.f-pv1)) * ((1.f-pv2)*(1.f-pv3)));
        splog += __logf((A0*A1) * (A2*A3));
        xsum  += (x0 + x1) + (x2 + x3);
        int s0_ = sslot[c+0], s1_ = sslot[c+1], s2_ = sslot[c+2], s3_ = sslot[c+3];
        if (s0_ >= 0) g_U[(size_t)s0_*BNA_ + bf] = __logf((1.f-pv0)/pv0);
        if (s1_ >= 0) g_U[(size_t)s1_*BNA_ + bf] = __logf((1.f-pv1)/pv1);
        if (s2_ >= 0) g_U[(size_t)s2_*BNA_ + bf] = __logf((1.f-pv2)/pv2);
        if (s3_ >= 0) g_U[(size_t)s3_*BNA_ + bf] = __logf((1.f-pv3)/pv3);
    }
    g_csp[bf] = xsum + splog;               // sum softplus(x_c)
    ((float*)g_cgeo)[4*bf + 3] = s;         // cgeo.w = s
}

// ---------------- K4: cost + topk, block per (b, valid-gt j), 2-level merge ----------------
#define TT_ 256
__global__ void k_costtopk() {
    int b = blockIdx.y, j = blockIdx.x;
    if (j >= g_nval[b]) return;
    int N = g_nfg[b];
    if (N == 0) return;

    float4 gb = g_vgtbox[b*G_ + j];
    int slot = g_slotofcls[b * NC_ + g_vgtcls[b*G_ + j]];
    float gl = gb.x - gb.z*0.5f, gr = gb.x + gb.z*0.5f;
    float gt_ = gb.y - gb.w*0.5f, gbm = gb.y + gb.w*0.5f;
    float areag = gb.z * gb.w;
    const float*  Up   = g_U + (size_t)slot * BNA_ + b * NA_;
    const float4* cbox = g_cbox + b * NA_;
    const float4* cgeo = g_cgeo + b * NA_;
    float2* cip = g_ci + (size_t)b * NA_ * G_;

    int wid = threadIdx.x >> 5, lane = threadIdx.x & 31;

    float lc[10], li[10];
    #pragma unroll
    for (int i = 0; i < 10; i++) { lc[i] = 3.0e38f; li[i] = 0.f; }

    for (int f = threadIdx.x; f < N; f += TT_) {
        float4 bb = cbox[f];
        float4 ge = cgeo[f];
        float  U  = Up[f];

        float bz2 = bb.z * 0.5f, bw2 = bb.w * 0.5f;
        float tlx = fmaxf(gl,  bb.x - bz2);
        float tly = fmaxf(gt_, bb.y - bw2);
        float brx = fminf(gr,  bb.x + bz2);
        float bry = fminf(gbm, bb.y + bw2);
        float en  = (tlx < brx && tly < bry) ? 1.f : 0.f;
        float inter = (brx - tlx) * (bry - tly) * en;
        float iou = inter / (areag + bb.z*bb.w - inter + 1e-12f);

        bool ib = (ge.x > gl) && (ge.x < gr) && (ge.y > gt_) && (ge.y < gbm);
        bool ic = (fabsf(ge.x - gb.x) < ge.z) && (fabsf(ge.y - gb.y) < ge.z);
        bool geom = ib && ic;

        float t = iou + 1e-8f;
        float cost = U - ge.w - 3.f * __logf(t) + (geom ? 0.f : 100000.f);

        cip[(size_t)f * G_ + j] = make_float2(cost, iou);
        ins_min10(lc, cost);
        ins_max10(li, iou);
    }

    // level 1: each warp merges its 32 sorted lists -> 10 values in shared
    __shared__ float swc[8*10], swi[8*10];
    for (int k = 0; k < 10; k++) {          // iou descending
        float bv = li[0]; int bl = lane;
        #pragma unroll
        for (int off = 16; off; off >>= 1) {
            float ov = __shfl_down_sync(0xffffffffu, bv, off);
            int   ol = __shfl_down_sync(0xffffffffu, bl, off);
            if (ov > bv || (ov == bv && ol < bl)) { bv = ov; bl = ol; }
        }
        bv = __shfl_sync(0xffffffffu, bv, 0);
        bl = __shfl_sync(0xffffffffu, bl, 0);
        if (lane == bl) {
            #pragma unroll
            for (int q = 0; q < 9; q++) li[q] = li[q+1];
            li[9] = -3.0e38f;
        }
        if (lane == 0) swi[wid*10 + k] = bv;
    }
    for (int k = 0; k < 10; k++) {          // cost ascending
        float bv = lc[0]; int bl = lane;
        #pragma unroll
        for (int off = 16; off; off >>= 1) {
            float ov = __shfl_down_sync(0xffffffffu, bv, off);
            int   ol = __shfl_down_sync(0xffffffffu, bl, off);
            if (ov < bv || (ov == bv && ol < bl)) { bv = ov; bl = ol; }
        }
        bv = __shfl_sync(0xffffffffu, bv, 0);
        bl = __shfl_sync(0xffffffffu, bl, 0);
        if (lane == bl) {
            #pragma unroll
            for (int q = 0; q < 9; q++) lc[q] = lc[q+1];
            lc[9] = 3.0e38f;
        }
        if (lane == 0) swc[wid*10 + k] = bv;
    }
    __syncthreads();

    // level 2: warp 0 merges 80 candidates
    if (wid != 0) return;
    #pragma unroll
    for (int i = 0; i < 10; i++) { lc[i] = 3.0e38f; li[i] = 0.f; }
    for (int i = lane; i < 80; i += 32) {
        ins_min10(lc, swc[i]);
        ins_max10(li, swi[i]);
    }

    float isum = 0.f;
    for (int k = 0; k < 10; k++) {
        float bv = li[0]; int bl = lane;
        #pragma unroll
        for (int off = 16; off; off >>= 1) {
            float ov = __shfl_down_sync(0xffffffffu, bv, off);
            int   ol = __shfl_down_sync(0xffffffffu, bl, off);
            if (ov > bv || (ov == bv && ol < bl)) { bv = ov; bl = ol; }
        }
        bv = __shfl_sync(0xffffffffu, bv, 0);
        bl = __shfl_sync(0xffffffffu, bl, 0);
        if (lane == bl) {
            #pragma unroll
            for (int q = 0; q < 9; q++) li[q] = li[q+1];
            li[9] = -3.0e38f;
        }
        isum += bv;
    }
    int dynk = (int)isum;
    if (dynk < 1) dynk = 1;
    if (dynk > 10) dynk = 10;
    if (dynk > N) dynk = N;

    float thr = 0.f;
    for (int k = 0; k < 10; k++) {
        float bv = lc[0]; int bl = lane;
        #pragma unroll
        for (int off = 16; off; off >>= 1) {
            float ov = __shfl_down_sync(0xffffffffu, bv, off);
            int   ol = __shfl_down_sync(0xffffffffu, bl, off);
            if (ov < bv || (ov == bv && ol < bl)) { bv = ov; bl = ol; }
        }
        bv = __shfl_sync(0xffffffffu, bv, 0);
        bl = __shfl_sync(0xffffffffu, bl, 0);
        if (lane == bl) {
            #pragma unroll
            for (int q = 0; q < 9; q++) lc[q] = lc[q+1];
            lc[9] = 3.0e38f;
        }
        if (k == dynk - 1) thr = bv;
    }
    if (lane == 0) g_thr[b*G_ + j] = thr;
}

// ---------------- K5: resolve (warp per fg anchor), coalesced ci reads ----------------
#define RW_ 8
__global__ void k_resolve(const float* __restrict__ out0,
                          const float* __restrict__ out1,
                          const float* __restrict__ out2) {
    int b = blockIdx.y;
    int wid = threadIdx.x >> 5, lane = threadIdx.x & 31;
    int f = blockIdx.x * RW_ + wid;
    int nfg = g_nfg[b];
    int nv  = g_nval[b];

    float liou = 0.f, lobj = 0.f, lcls = 0.f, lfg = 0.f;

    if (f < nfg) {
        int bf = b * NA_ + f;
        const float2* cip = g_ci + (size_t)bf * G_;

        int j0 = lane, j1 = lane + 32;
        bool v0 = j0 < nv, v1 = j1 < nv;
        float2 a0 = v0 ? cip[j0] : make_float2(3.4e38f, 0.f);
        float2 a1 = v1 ? cip[j1] : make_float2(3.4e38f, 0.f);
        float t0 = v0 ? g_thr[b*G_ + j0] : 0.f;
        float t1 = v1 ? g_thr[b*G_ + j1] : 0.f;
        bool m0 = v0 && (a0.x <= t0);
        bool m1 = v1 && (a1.x <= t1);
        int count = __popc(__ballot_sync(0xffffffffu, m0))
                  + __popc(__ballot_sync(0xffffffffu, m1));

        float cmin = fminf(a0.x, a1.x);
        int   jmin = (a0.x <= a1.x) ? j0 : j1;
        #pragma unroll
        for (int off = 16; off; off >>= 1) {
            float ov = __shfl_xor_sync(0xffffffffu, cmin, off);
            int   oj = __shfl_xor_sync(0xffffffffu, jmin, off);
            if (ov < cmin || (ov == cmin && oj < jmin)) { cmin = ov; jmin = oj; }
        }

        if (count > 1) {
            m0 = m0 && (j0 == jmin);
            m1 = m1 && (j1 == jmin);
        }
        unsigned fb0 = __ballot_sync(0xffffffffu, m0);
        unsigned fb1 = __ballot_sync(0xffffffffu, m1);
        bool fgfin = (fb0 | fb1) != 0u;

        if (fgfin) {
            int mj = fb0 ? (__ffs(fb0) - 1) : (32 + __ffs(fb1) - 1);

            float io = 0.f;
            if (m0) io += a0.y;
            if (m1) io += a1.y;
            #pragma unroll
            for (int off = 16; off; off >>= 1)
                io += __shfl_xor_sync(0xffffffffu, io, off);
            float piou = io;

            if (lane == (mj & 31)) {
                float4 gbx = g_vgtbox[b*G_ + mj];
                float4 bb = g_cbox[bf];
                float tlx = fmaxf(bb.x - bb.z*0.5f, gbx.x - gbx.z*0.5f);
                float tly = fmaxf(bb.y - bb.w*0.5f, gbx.y - gbx.w*0.5f);
                float brx = fminf(bb.x + bb.z*0.5f, gbx.x + gbx.z*0.5f);
                float bry = fminf(bb.y + bb.w*0.5f, gbx.y + gbx.w*0.5f);
                float en  = (tlx < brx && tly < bry) ? 1.f : 0.f;
                float inter = fmaxf(brx - tlx, 0.f) * fmaxf(bry - tly, 0.f) * en;
                float uni = bb.z*bb.w + gbx.z*gbx.w - inter + 1e-16f;
                float iou = inter / uni;
                liou = 1.f - iou * iou;
                lfg  = 1.f;
                lobj = -g_cobj[bf];   // softplus(obj) accumulated in decode

                int mcls = g_vgtcls[b*G_ + mj];
                int a = g_flist[bf];
                int hw, W, HW; float st;
                anchor_map(a, hw, W, HW, st);
                const float* src = (a < 6400) ? out0 : (a < 8000) ? out1 : out2;
                float xm = __ldg(&src[((size_t)b * 85 + 5 + mcls) * HW + hw]);
                lcls = g_csp[bf] - xm * piou;
            }
        }
    }

    #pragma unroll
    for (int off = 16; off; off >>= 1) {
        liou += __shfl_down_sync(0xffffffffu, liou, off);
        lobj += __shfl_down_sync(0xffffffffu, lobj, off);
        lcls += __shfl_down_sync(0xffffffffu, lcls, off);
        lfg  += __shfl_down_sync(0xffffffffu, lfg,  off);
    }
    __shared__ float s4[RW_][4];
    if (lane == 0) { s4[wid][0] = liou; s4[wid][1] = lobj; s4[wid][2] = lcls; s4[wid][3] = lfg; }
    __syncthreads();
    if (threadIdx.x == 0) {
        float a0 = 0.f, a1 = 0.f, a2 = 0.f, a3 = 0.f;
        for (int i = 0; i < RW_; i++) { a0 += s4[i][0]; a1 += s4[i][1]; a2 += s4[i][2]; a3 += s4[i][3]; }
        if (a0 != 0.f) atomicAdd(&g_accb[b][0], (double)a0);
        if (a1 != 0.f) atomicAdd(&g_accb[b][1], (double)a1);
        if (a2 != 0.f) atomicAdd(&g_accb[b][2], (double)a2);
        if (a3 != 0.f) atomicAdd(&g_accb[b][3], (double)a3);
    }
}

// ---------------- K6: finalize ----------------
__global__ void k_final(float* __restrict__ out) {
    if (threadIdx.x == 0) {
        double si = 0.0, so = 0.0, sc = 0.0, nf = 0.0;
        for (int b = 0; b < B_; b++) {
            si += g_accb[b][0]; so += g_accb[b][1];
            sc += g_accb[b][2]; nf += g_accb[b][3];
        }
        if (nf < 1.0) nf = 1.0;
        out[0] = (float)((5.0 * si + so + sc) / nf);
    }
}

// ---------------- launch ----------------
extern "C" void kernel_launch(void* const* d_in, const int* in_sizes, int n_in,
                              void* d_out, int out_size) {
    const float* out0   = (const float*)d_in[0];
    const float* out1   = (const float*)d_in[1];
    const float* out2   = (const float*)d_in[2];
    const float* labels = (const float*)d_in[3];
    float* out = (float*)d_out;

    k_gt<<<B_, 128>>>(labels);
    {
        dim3 g((NA_ + 255) / 256, B_);
        k_decode<<<g, 256>>>(out0, out1, out2);
    }
    {
        dim3 g((NA_ + 255) / 256, B_);
        k_stats<<<g, 256>>>(out0, out1, out2);
    }
    {
        dim3 g(G_, B_);
        k_costtopk<<<g, TT_>>>();
    }
    {
        dim3 g((NA_ + RW_ - 1) / RW_, B_);
        k_resolve<<<g, 256>>>(out0, out1, out2);
    }
    k_final<<<1, 32>>>(out);
}

// round 15
// speedup vs baseline: 1.3880x; 1.0453x over previous
#include <cuda_runtime.h>
#include <math.h>

#define B_  32
#define G_  50
#define NC_ 80
#define NA_ 8400
#define BNA_ (B_*NA_)

// ---------------- device scratch ----------------
__device__ int           g_flist[BNA_];
__device__ int           g_nfg [B_];
__device__ float4        g_cbox[BNA_];          // decoded box
__device__ float4        g_cgeo[BNA_];          // cx, cy, rs, s(from stats)
__device__ float         g_cBo [BNA_];          // 1+exp(-obj)
__device__ float         g_csp [BNA_];          // sum softplus(x_c)
__device__ float         g_cobj[BNA_];          // obj logit
__device__ float         g_U   [G_*BNA_];       // slot planes: log((1-pv)/pv)
__device__ int           g_slotofcls[B_*NC_];   // class -> slot (-1 unused)
__device__ float4        g_vgtbox[B_*G_];
__device__ int           g_vgtcls[B_*G_];
__device__ int           g_nval [B_];
__device__ float         g_cost[B_*G_*NA_];     // [b][j][f] coalesced writes
__device__ float         g_thr [B_*G_];
__device__ double        g_accb[B_][4];

__device__ __forceinline__ void anchor_map(int a, int& hw, int& W, int& HW, float& st) {
    if (a < 6400)      { hw = a;        W = 80; HW = 6400; st = 8.f;  }
    else if (a < 8000) { hw = a - 6400; W = 40; HW = 1600; st = 16.f; }
    else               { hw = a - 8000; W = 20; HW = 400;  st = 32.f; }
}

__device__ __forceinline__ void ins_min10(float (&t)[10], float c) {
    if (c < t[9]) {
        t[9] = c;
        #pragma unroll
        for (int j = 9; j > 0; j--) {
            float lo = fminf(t[j-1], t[j]);
            float hi = fmaxf(t[j-1], t[j]);
            t[j-1] = lo; t[j] = hi;
        }
    }
}
__device__ __forceinline__ void ins_max10(float (&t)[10], float c) {
    if (c > t[9]) {
        t[9] = c;
        #pragma unroll
        for (int j = 9; j > 0; j--) {
            float hi = fmaxf(t[j-1], t[j]);
            float lo = fminf(t[j-1], t[j]);
            t[j-1] = hi; t[j] = lo;
        }
    }
}

// exact pairwise iou (single canonical op order used by BOTH costtopk and resolve)
__device__ __forceinline__ float pair_iou(float4 gb, float4 bb) {
    float gl = gb.x - gb.z*0.5f, gr = gb.x + gb.z*0.5f;
    float gt_ = gb.y - gb.w*0.5f, gbm = gb.y + gb.w*0.5f;
    float bz2 = bb.z * 0.5f, bw2 = bb.w * 0.5f;
    float tlx = fmaxf(gl,  bb.x - bz2);
    float tly = fmaxf(gt_, bb.y - bw2);
    float brx = fminf(gr,  bb.x + bz2);
    float bry = fminf(gbm, bb.y + bw2);
    float en  = (tlx < brx && tly < bry) ? 1.f : 0.f;
    float inter = (brx - tlx) * (bry - tly) * en;
    return inter / (gb.z*gb.w + bb.z*bb.w - inter + 1e-12f);
}

// ---------------- K1: gts + zero + valid compaction + class slot map ----------------
__global__ void k_gt(const float* __restrict__ labels) {
    int b = blockIdx.x;
    int tid = threadIdx.x;
    __shared__ unsigned um[3];
    __shared__ float4 sbox[G_];
    __shared__ int scls[G_];
    __shared__ unsigned char sv[G_];
    if (tid < 3) um[tid] = 0u;
    if (tid < 4) g_accb[b][tid] = 0.0;
    if (tid == 0) g_nfg[b] = 0;
    __syncthreads();

    if (tid < G_) {
        const float* l = labels + (b * G_ + tid) * 5;
        float c = l[0], x = l[1], y = l[2], w = l[3], h = l[4];
        bool val = (c + x + y + w + h) > 0.f;
        sv[tid] = val;
        sbox[tid] = make_float4(x, y, w, h);
        int ci = (int)c;
        scls[tid] = ci;
        if (val) atomicOr(&um[ci >> 5], 1u << (ci & 31));
    }
    __syncthreads();

    if (tid == 0) {
        int cnt = 0;
        for (int g = 0; g < G_; g++) {
            if (sv[g]) {
                g_vgtbox[b*G_ + cnt] = sbox[g];
                g_vgtcls[b*G_ + cnt] = scls[g];
                cnt++;
            }
        }
        g_nval[b] = cnt;
    }

    if (tid < NC_) {
        unsigned m0 = um[0], m1 = um[1], m2 = um[2];
        bool used = (tid < 32) ? ((m0 >> tid) & 1u)
                  : (tid < 64) ? ((m1 >> (tid - 32)) & 1u)
                               : ((m2 >> (tid - 64)) & 1u);
        int slot = -1;
        if (used) {
            int cnt;
            if (tid < 32) {
                cnt = __popc(m0 & ((tid == 0) ? 0u : ((1u << tid) - 1u)));
            } else if (tid < 64) {
                int t = tid - 32;
                cnt = __popc(m0) + __popc(m1 & ((t == 0) ? 0u : ((1u << t) - 1u)));
            } else {
                int t = tid - 64;
                cnt = __popc(m0) + __popc(m1) + __popc(m2 & ((t == 0) ? 0u : ((1u << t) - 1u)));
            }
            slot = cnt;
        }
        g_slotofcls[b * NC_ + tid] = slot;
    }
}

// ---------------- K2: decode + fg + compact staging + obj softplus ----------------
__global__ void k_decode(const float* __restrict__ out0,
                         const float* __restrict__ out1,
                         const float* __restrict__ out2) {
    __shared__ float4 svb[G_];
    __shared__ int snv;
    int b = blockIdx.y;
    if (threadIdx.x == 0) snv = g_nval[b];
    if (threadIdx.x < G_) svb[threadIdx.x] = g_vgtbox[b*G_ + threadIdx.x];
    __syncthreads();
    int nv = snv;

    int a = blockIdx.x * blockDim.x + threadIdx.x;
    int lane = threadIdx.x & 31;
    float softplus_obj = 0.f;
    bool fg = false;
    float4 box = make_float4(0.f, 0.f, 0.f, 0.f);
    float Bo = 0.f, to = 0.f, cx = 0.f, cy = 0.f, rs = 0.f;

    if (a < NA_) {
        int hw, W, HW; float st;
        anchor_map(a, hw, W, HW, st);
        const float* src = (a < 6400) ? out0 : (a < 8000) ? out1 : out2;
        const float* p = src + (size_t)b * 85 * HW + hw;

        float tx = p[0], ty = p[HW], tw = p[2*HW], th = p[3*HW];
        to = p[4*HW];
        int h = hw / W, w = hw - h * W;
        box = make_float4((tx + (float)w) * st, (ty + (float)h) * st,
                          __expf(tw) * st, __expf(th) * st);
        Bo = 1.f + __expf(-to);
        softplus_obj = fmaxf(to, 0.f) + __logf(1.f + __expf(-fabsf(to)));

        cx = ((float)w + 0.5f) * st;
        cy = ((float)h + 0.5f) * st;
        rs = 2.5f * st;
        for (int j = 0; j < nv; j++) {
            float4 gb = svb[j];
            bool ib = (cx > gb.x - 0.5f*gb.z) && (cx < gb.x + 0.5f*gb.z) &&
                      (cy > gb.y - 0.5f*gb.w) && (cy < gb.y + 0.5f*gb.w);
            bool ic = (fabsf(cx - gb.x) < rs) && (fabsf(cy - gb.y) < rs);
            fg |= (ib | ic);
        }
    }

    unsigned bal = __ballot_sync(0xffffffffu, fg);
    if (bal) {
        int leader = __ffs(bal) - 1;
        int base = 0;
        if (lane == leader) base = atomicAdd(&g_nfg[b], __popc(bal));
        base = __shfl_sync(0xffffffffu, base, leader);
        if (fg) {
            int f = base + __popc(bal & ((1u << lane) - 1));
            int bf = b * NA_ + f;
            g_flist[bf] = a;
            g_cbox[bf] = box;
            g_cgeo[bf] = make_float4(cx, cy, rs, 0.f);
            g_cBo [bf] = Bo;
            g_cobj[bf] = to;
        }
    }

    #pragma unroll
    for (int off = 16; off; off >>= 1)
        softplus_obj += __shfl_down_sync(0xffffffffu, softplus_obj, off);
    __shared__ float swsum[8];
    int wid = threadIdx.x >> 5;
    if (lane == 0) swsum[wid] = softplus_obj;
    __syncthreads();
    if (threadIdx.x == 0) {
        float t = 0.f;
        for (int i = 0; i < 8; i++) t += swsum[i];
        atomicAdd(&g_accb[b][1], (double)t);
    }
}

// ---------------- K3: dense per-fg-anchor stats (slot-compressed U planes) ----------------
__global__ void k_stats(const float* __restrict__ out0,
                        const float* __restrict__ out1,
                        const float* __restrict__ out2) {
    __shared__ int sslot[NC_];
    int b = blockIdx.y;
    if (threadIdx.x < NC_) sslot[threadIdx.x] = g_slotofcls[b * NC_ + threadIdx.x];
    __syncthreads();

    int f = blockIdx.x * blockDim.x + threadIdx.x;
    if (f >= g_nfg[b]) return;
    int bf = b * NA_ + f;
    int a = g_flist[bf];
    int hw, W, HW; float st;
    anchor_map(a, hw, W, HW, st);
    const float* src = (a < 6400) ? out0 : (a < 8000) ? out1 : out2;
    const float* p = src + ((size_t)b * 85 + 5) * HW + hw;
    float Bo = g_cBo[bf];

    float s = 0.f, splog = 0.f, xsum = 0.f;
    #pragma unroll 2
    for (int c = 0; c < NC_; c += 4) {
        float x0 = __ldg(&p[(c+0)*HW]);
        float x1 = __ldg(&p[(c+1)*HW]);
        float x2 = __ldg(&p[(c+2)*HW]);
        float x3 = __ldg(&p[(c+3)*HW]);
        float A0 = 1.f + __expf(-x0);
        float A1 = 1.f + __expf(-x1);
        float A2 = 1.f + __expf(-x2);
        float A3 = 1.f + __expf(-x3);
        float pv0 = fminf(fmaxf(rsqrtf(A0*Bo), 1e-7f), 1.f - 1e-6f);
        float pv1 = fminf(fmaxf(rsqrtf(A1*Bo), 1e-7f), 1.f - 1e-6f);
        float pv2 = fminf(fmaxf(rsqrtf(A2*Bo), 1e-7f), 1.f - 1e-6f);
        float pv3 = fminf(fmaxf(rsqrtf(A3*Bo), 1e-7f), 1.f - 1e-6f);
        s     += __logf(((1.f-pv0)*(1.f-pv1)) * ((1.f-pv2)*(1.f-pv3)));
        splog += __logf((A0*A1) * (A2*A3));
        xsum  += (x0 + x1) + (x2 + x3);
        int s0_ = sslot[c+0], s1_ = sslot[c+1], s2_ = sslot[c+2], s3_ = sslot[c+3];
        if (s0_ >= 0) g_U[(size_t)s0_*BNA_ + bf] = __logf((1.f-pv0)/pv0);
        if (s1_ >= 0) g_U[(size_t)s1_*BNA_ + bf] = __logf((1.f-pv1)/pv1);
        if (s2_ >= 0) g_U[(size_t)s2_*BNA_ + bf] = __logf((1.f-pv2)/pv2);
        if (s3_ >= 0) g_U[(size_t)s3_*BNA_ + bf] = __logf((1.f-pv3)/pv3);
    }
    g_csp[bf] = xsum + splog;
    ((float*)g_cgeo)[4*bf + 3] = s;
}

// ---------------- K4: cost + topk, block per (b, valid j), coalesced stores ----------------
#define TT_ 256
__global__ void k_costtopk() {
    int b = blockIdx.y, j = blockIdx.x;
    if (j >= g_nval[b]) return;
    int N = g_nfg[b];
    if (N == 0) return;

    float4 gb = g_vgtbox[b*G_ + j];
    int slot = g_slotofcls[b * NC_ + g_vgtcls[b*G_ + j]];
    float gl = gb.x - gb.z*0.5f, gr = gb.x + gb.z*0.5f;
    float gt_ = gb.y - gb.w*0.5f, gbm = gb.y + gb.w*0.5f;
    const float*  Up   = g_U + (size_t)slot * BNA_ + b * NA_;
    const float4* cbox = g_cbox + b * NA_;
    const float4* cgeo = g_cgeo + b * NA_;
    float* crow = g_cost + (size_t)(b * G_ + j) * NA_;

    int wid = threadIdx.x >> 5, lane = threadIdx.x & 31;

    float lc[10], li[10];
    #pragma unroll
    for (int i = 0; i < 10; i++) { lc[i] = 3.0e38f; li[i] = 0.f; }

    // unroll x2 for MLP
    int f = threadIdx.x;
    for (; f + TT_ < N; f += 2*TT_) {
        float4 bb0 = __ldg(&cbox[f]);
        float4 bb1 = __ldg(&cbox[f + TT_]);
        float4 ge0 = __ldg(&cgeo[f]);
        float4 ge1 = __ldg(&cgeo[f + TT_]);
        float  U0  = __ldg(&Up[f]);
        float  U1  = __ldg(&Up[f + TT_]);

        float iou0 = pair_iou(gb, bb0);
        float iou1 = pair_iou(gb, bb1);

        bool geom0 = (ge0.x > gl) && (ge0.x < gr) && (ge0.y > gt_) && (ge0.y < gbm)
                   && (fabsf(ge0.x - gb.x) < ge0.z) && (fabsf(ge0.y - gb.y) < ge0.z);
        bool geom1 = (ge1.x > gl) && (ge1.x < gr) && (ge1.y > gt_) && (ge1.y < gbm)
                   && (fabsf(ge1.x - gb.x) < ge1.z) && (fabsf(ge1.y - gb.y) < ge1.z);

        float c0 = __ldg(&Up[f])*0.f + U0 - ge0.w - 3.f * __logf(iou0 + 1e-8f) + (geom0 ? 0.f : 100000.f);
        float c1 = U1 - ge1.w - 3.f * __logf(iou1 + 1e-8f) + (geom1 ? 0.f : 100000.f);

        crow[f]       = c0;
        crow[f + TT_] = c1;
        ins_min10(lc, c0);
        ins_min10(lc, c1);
        ins_max10(li, iou0);
        ins_max10(li, iou1);
    }
    for (; f < N; f += TT_) {
        float4 bb = __ldg(&cbox[f]);
        float4 ge = __ldg(&cgeo[f]);
        float  U  = __ldg(&Up[f]);
        float iou = pair_iou(gb, bb);
        bool geom = (ge.x > gl) && (ge.x < gr) && (ge.y > gt_) && (ge.y < gbm)
                  && (fabsf(ge.x - gb.x) < ge.z) && (fabsf(ge.y - gb.y) < ge.z);
        float c = U - ge.w - 3.f * __logf(iou + 1e-8f) + (geom ? 0.f : 100000.f);
        crow[f] = c;
        ins_min10(lc, c);
        ins_max10(li, iou);
    }

    // level 1: per-warp merge -> 10 values each in shared
    __shared__ float swc[8*10], swi[8*10];
    for (int k = 0; k < 10; k++) {          // iou descending
        float bv = li[0]; int bl = lane;
        #pragma unroll
        for (int off = 16; off; off >>= 1) {
            float ov = __shfl_down_sync(0xffffffffu, bv, off);
            int   ol = __shfl_down_sync(0xffffffffu, bl, off);
            if (ov > bv || (ov == bv && ol < bl)) { bv = ov; bl = ol; }
        }
        bv = __shfl_sync(0xffffffffu, bv, 0);
        bl = __shfl_sync(0xffffffffu, bl, 0);
        if (lane == bl) {
            #pragma unroll
            for (int q = 0; q < 9; q++) li[q] = li[q+1];
            li[9] = -3.0e38f;
        }
        if (lane == 0) swi[wid*10 + k] = bv;
    }
    for (int k = 0; k < 10; k++) {          // cost ascending
        float bv = lc[0]; int bl = lane;
        #pragma unroll
        for (int off = 16; off; off >>= 1) {
            float ov = __shfl_down_sync(0xffffffffu, bv, off);
            int   ol = __shfl_down_sync(0xffffffffu, bl, off);
            if (ov < bv || (ov == bv && ol < bl)) { bv = ov; bl = ol; }
        }
        bv = __shfl_sync(0xffffffffu, bv, 0);
        bl = __shfl_sync(0xffffffffu, bl, 0);
        if (lane == bl) {
            #pragma unroll
            for (int q = 0; q < 9; q++) lc[q] = lc[q+1];
            lc[9] = 3.0e38f;
        }
        if (lane == 0) swc[wid*10 + k] = bv;
    }
    __syncthreads();

    // level 2: warp 0 merges 80 candidates
    if (wid != 0) return;
    #pragma unroll
    for (int i = 0; i < 10; i++) { lc[i] = 3.0e38f; li[i] = 0.f; }
    for (int i = lane; i < 80; i += 32) {
        ins_min10(lc, swc[i]);
        ins_max10(li, swi[i]);
    }

    float isum = 0.f;
    for (int k = 0; k < 10; k++) {
        float bv = li[0]; int bl = lane;
        #pragma unroll
        for (int off = 16; off; off >>= 1) {
            float ov = __shfl_down_sync(0xffffffffu, bv, off);
            int   ol = __shfl_down_sync(0xffffffffu, bl, off);
            if (ov > bv || (ov == bv && ol < bl)) { bv = ov; bl = ol; }
        }
        bv = __shfl_sync(0xffffffffu, bv, 0);
        bl = __shfl_sync(0xffffffffu, bl, 0);
        if (lane == bl) {
            #pragma unroll
            for (int q = 0; q < 9; q++) li[q] = li[q+1];
            li[9] = -3.0e38f;
        }
        isum += bv;
    }
    int dynk = (int)isum;
    if (dynk < 1) dynk = 1;
    if (dynk > 10) dynk = 10;
    if (dynk > N) dynk = N;

    float thr = 0.f;
    for (int k = 0; k < 10; k++) {
        float bv = lc[0]; int bl = lane;
        #pragma unroll
        for (int off = 16; off; off >>= 1) {
            float ov = __shfl_down_sync(0xffffffffu, bv, off);
            int   ol = __shfl_down_sync(0xffffffffu, bl, off);
            if (ov < bv || (ov == bv && ol < bl)) { bv = ov; bl = ol; }
        }
        bv = __shfl_sync(0xffffffffu, bv, 0);
        bl = __shfl_sync(0xffffffffu, bl, 0);
        if (lane == bl) {
            #pragma unroll
            for (int q = 0; q < 9; q++) lc[q] = lc[q+1];
            lc[9] = 3.0e38f;
        }
        if (k == dynk - 1) thr = bv;
    }
    if (lane == 0) g_thr[b*G_ + j] = thr;
}

// ---------------- K5: resolve (warp per fg anchor), iou recomputed ----------------
#define RW_ 8
__global__ void k_resolve(const float* __restrict__ out0,
                          const float* __restrict__ out1,
                          const float* __restrict__ out2) {
    int b = blockIdx.y;
    int wid = threadIdx.x >> 5, lane = threadIdx.x & 31;
    int f = blockIdx.x * RW_ + wid;
    int nfg = g_nfg[b];
    int nv  = g_nval[b];

    float liou = 0.f, lobj = 0.f, lcls = 0.f, lfg = 0.f;

    if (f < nfg) {
        int bf = b * NA_ + f;

        int j0 = lane, j1 = lane + 32;
        bool v0 = j0 < nv, v1 = j1 < nv;
        float c0 = v0 ? __ldg(&g_cost[(size_t)(b*G_ + j0) * NA_ + f]) : 3.4e38f;
        float c1 = v1 ? __ldg(&g_cost[(size_t)(b*G_ + j1) * NA_ + f]) : 3.4e38f;
        float t0 = v0 ? g_thr[b*G_ + j0] : 0.f;
        float t1 = v1 ? g_thr[b*G_ + j1] : 0.f;
        bool m0 = v0 && (c0 <= t0);
        bool m1 = v1 && (c1 <= t1);
        int count = __popc(__ballot_sync(0xffffffffu, m0))
                  + __popc(__ballot_sync(0xffffffffu, m1));

        float cmin = fminf(c0, c1);
        int   jmin = (c0 <= c1) ? j0 : j1;
        #pragma unroll
        for (int off = 16; off; off >>= 1) {
            float ov = __shfl_xor_sync(0xffffffffu, cmin, off);
            int   oj = __shfl_xor_sync(0xffffffffu, jmin, off);
            if (ov < cmin || (ov == cmin && oj < jmin)) { cmin = ov; jmin = oj; }
        }

        if (count > 1) {
            m0 = m0 && (j0 == jmin);
            m1 = m1 && (j1 == jmin);
        }
        unsigned fb0 = __ballot_sync(0xffffffffu, m0);
        unsigned fb1 = __ballot_sync(0xffffffffu, m1);
        bool fgfin = (fb0 | fb1) != 0u;

        if (fgfin) {
            int mj = fb0 ? (__ffs(fb0) - 1) : (32 + __ffs(fb1) - 1);

            // owner lane computes losses (match set is exactly one gt)
            if (lane == (mj & 31)) {
                float4 gbx = g_vgtbox[b*G_ + mj];
                float4 bb = g_cbox[bf];
                // piou: bit-identical recompute of costtopk's pairwise iou
                float piou = pair_iou(gbx, bb);

                // iou loss (clipped variant)
                float tlx = fmaxf(bb.x - bb.z*0.5f, gbx.x - gbx.z*0.5f);
                float tly = fmaxf(bb.y - bb.w*0.5f, gbx.y - gbx.w*0.5f);
                float brx = fminf(bb.x + bb.z*0.5f, gbx.x + gbx.z*0.5f);
                float bry = fminf(bb.y + bb.w*0.5f, gbx.y + gbx.w*0.5f);
                float en  = (tlx < brx && tly < bry) ? 1.f : 0.f;
                float inter = fmaxf(brx - tlx, 0.f) * fmaxf(bry - tly, 0.f) * en;
                float uni = bb.z*bb.w + gbx.z*gbx.w - inter + 1e-16f;
                float iou = inter / uni;
                liou = 1.f - iou * iou;
                lfg  = 1.f;
                lobj = -g_cobj[bf];   // softplus(obj) accumulated in decode

                int mcls = g_vgtcls[b*G_ + mj];
                int a = g_flist[bf];
                int hw, W, HW; float st;
                anchor_map(a, hw, W, HW, st);
                const float* src = (a < 6400) ? out0 : (a < 8000) ? out1 : out2;
                float xm = __ldg(&src[((size_t)b * 85 + 5 + mcls) * HW + hw]);
                lcls = g_csp[bf] - xm * piou;
            }
        }
    }

    #pragma unroll
    for (int off = 16; off; off >>= 1) {
        liou += __shfl_down_sync(0xffffffffu, liou, off);
        lobj += __shfl_down_sync(0xffffffffu, lobj, off);
        lcls += __shfl_down_sync(0xffffffffu, lcls, off);
        lfg  += __shfl_down_sync(0xffffffffu, lfg,  off);
    }
    __shared__ float s4[RW_][4];
    if (lane == 0) { s4[wid][0] = liou; s4[wid][1] = lobj; s4[wid][2] = lcls; s4[wid][3] = lfg; }
    __syncthreads();
    if (threadIdx.x == 0) {
        float a0 = 0.f, a1 = 0.f, a2 = 0.f, a3 = 0.f;
        for (int i = 0; i < RW_; i++) { a0 += s4[i][0]; a1 += s4[i][1]; a2 += s4[i][2]; a3 += s4[i][3]; }
        if (a0 != 0.f) atomicAdd(&g_accb[b][0], (double)a0);
        if (a1 != 0.f) atomicAdd(&g_accb[b][1], (double)a1);
        if (a2 != 0.f) atomicAdd(&g_accb[b][2], (double)a2);
        if (a3 != 0.f) atomicAdd(&g_accb[b][3], (double)a3);
    }
}

// ---------------- K6: finalize ----------------
__global__ void k_final(float* __restrict__ out) {
    if (threadIdx.x == 0) {
        double si = 0.0, so = 0.0, sc = 0.0, nf = 0.0;
        for (int b = 0; b < B_; b++) {
            si += g_accb[b][0]; so += g_accb[b][1];
            sc += g_accb[b][2]; nf += g_accb[b][3];
        }
        if (nf < 1.0) nf = 1.0;
        out[0] = (float)((5.0 * si + so + sc) / nf);
    }
}

// ---------------- launch ----------------
extern "C" void kernel_launch(void* const* d_in, const int* in_sizes, int n_in,
                              void* d_out, int out_size) {
    const float* out0   = (const float*)d_in[0];
    const float* out1   = (const float*)d_in[1];
    const float* out2   = (const float*)d_in[2];
    const float* labels = (const float*)d_in[3];
    float* out = (float*)d_out;

    k_gt<<<B_, 128>>>(labels);
    {
        dim3 g((NA_ + 255) / 256, B_);
        k_decode<<<g, 256>>>(out0, out1, out2);
    }
    {
        dim3 g((NA_ + 255) / 256, B_);
        k_stats<<<g, 256>>>(out0, out1, out2);
    }
    {
        dim3 g(G_, B_);
        k_costtopk<<<g, TT_>>>();
    }
    {
        dim3 g((NA_ + RW_ - 1) / RW_, B_);
        k_resolve<<<g, 256>>>(out0, out1, out2);
    }
    k_final<<<1, 32>>>(out);
}

// round 16
// speedup vs baseline: 1.8716x; 1.3484x over previous
#include <cuda_runtime.h>
#include <math.h>

#define B_  32
#define G_  50
#define NC_ 80
#define NA_ 8400
#define BNA_ (B_*NA_)

// ---------------- device scratch ----------------
__device__ int           g_flist[BNA_];
__device__ int           g_nfg [B_];
__device__ float4        g_cbox[BNA_];          // decoded box
__device__ float4        g_cgeo[BNA_];          // cx, cy, rs, s(from stats)
__device__ float         g_cBo [BNA_];          // 1+exp(-obj)
__device__ float         g_csp [BNA_];          // sum softplus(x_c)
__device__ float         g_cobj[BNA_];          // obj logit
__device__ float         g_U   [G_*BNA_];       // slot planes: log((1-pv)/pv)
__device__ int           g_slotofcls[B_*NC_];   // class -> slot (-1 unused)
__device__ float4        g_vgtbox[B_*G_];
__device__ int           g_vgtcls[B_*G_];
__device__ int           g_nval [B_];
__device__ float         g_cost[B_*G_*NA_];     // [b][j][f] coalesced writes
__device__ float         g_thr [B_*G_];
__device__ double        g_accb[B_][4];

__device__ __forceinline__ void anchor_map(int a, int& hw, int& W, int& HW, float& st) {
    if (a < 6400)      { hw = a;        W = 80; HW = 6400; st = 8.f;  }
    else if (a < 8000) { hw = a - 6400; W = 40; HW = 1600; st = 16.f; }
    else               { hw = a - 8000; W = 20; HW = 400;  st = 32.f; }
}

__device__ __forceinline__ void ins_min10(float (&t)[10], float c) {
    if (c < t[9]) {
        t[9] = c;
        #pragma unroll
        for (int j = 9; j > 0; j--) {
            float lo = fminf(t[j-1], t[j]);
            float hi = fmaxf(t[j-1], t[j]);
            t[j-1] = lo; t[j] = hi;
        }
    }
}
__device__ __forceinline__ void ins_max10(float (&t)[10], float c) {
    if (c > t[9]) {
        t[9] = c;
        #pragma unroll
        for (int j = 9; j > 0; j--) {
            float hi = fmaxf(t[j-1], t[j]);
            float lo = fminf(t[j-1], t[j]);
            t[j-1] = hi; t[j] = lo;
        }
    }
}

// exact pairwise iou (single canonical op order used by BOTH costtopk and resolve)
__device__ __forceinline__ float pair_iou(float4 gb, float4 bb) {
    float gl = gb.x - gb.z*0.5f, gr = gb.x + gb.z*0.5f;
    float gt_ = gb.y - gb.w*0.5f, gbm = gb.y + gb.w*0.5f;
    float bz2 = bb.z * 0.5f, bw2 = bb.w * 0.5f;
    float tlx = fmaxf(gl,  bb.x - bz2);
    float tly = fmaxf(gt_, bb.y - bw2);
    float brx = fminf(gr,  bb.x + bz2);
    float bry = fminf(gbm, bb.y + bw2);
    float en  = (tlx < brx && tly < bry) ? 1.f : 0.f;
    float inter = (brx - tlx) * (bry - tly) * en;
    return inter / (gb.z*gb.w + bb.z*bb.w - inter + 1e-12f);
}

// ---------------- K1: gts + zero + valid compaction + class slot map ----------------
__global__ void k_gt(const float* __restrict__ labels) {
    int b = blockIdx.x;
    int tid = threadIdx.x;
    __shared__ unsigned um[3];
    __shared__ float4 sbox[G_];
    __shared__ int scls[G_];
    __shared__ unsigned char sv[G_];
    if (tid < 3) um[tid] = 0u;
    if (tid < 4) g_accb[b][tid] = 0.0;
    if (tid == 0) g_nfg[b] = 0;
    __syncthreads();

    if (tid < G_) {
        const float* l = labels + (b * G_ + tid) * 5;
        float c = l[0], x = l[1], y = l[2], w = l[3], h = l[4];
        bool val = (c + x + y + w + h) > 0.f;
        sv[tid] = val;
        sbox[tid] = make_float4(x, y, w, h);
        int ci = (int)c;
        scls[tid] = ci;
        if (val) atomicOr(&um[ci >> 5], 1u << (ci & 31));
    }
    __syncthreads();

    if (tid == 0) {
        int cnt = 0;
        for (int g = 0; g < G_; g++) {
            if (sv[g]) {
                g_vgtbox[b*G_ + cnt] = sbox[g];
                g_vgtcls[b*G_ + cnt] = scls[g];
                cnt++;
            }
        }
        g_nval[b] = cnt;
    }

    if (tid < NC_) {
        unsigned m0 = um[0], m1 = um[1], m2 = um[2];
        bool used = (tid < 32) ? ((m0 >> tid) & 1u)
                  : (tid < 64) ? ((m1 >> (tid - 32)) & 1u)
                               : ((m2 >> (tid - 64)) & 1u);
        int slot = -1;
        if (used) {
            int cnt;
            if (tid < 32) {
                cnt = __popc(m0 & ((tid == 0) ? 0u : ((1u << tid) - 1u)));
            } else if (tid < 64) {
                int t = tid - 32;
                cnt = __popc(m0) + __popc(m1 & ((t == 0) ? 0u : ((1u << t) - 1u)));
            } else {
                int t = tid - 64;
                cnt = __popc(m0) + __popc(m1) + __popc(m2 & ((t == 0) ? 0u : ((1u << t) - 1u)));
            }
            slot = cnt;
        }
        g_slotofcls[b * NC_ + tid] = slot;
    }
}

// ---------------- K2: decode + fg + compact staging + obj softplus ----------------
__global__ void k_decode(const float* __restrict__ out0,
                         const float* __restrict__ out1,
                         const float* __restrict__ out2) {
    __shared__ float4 svb[G_];
    __shared__ int snv;
    int b = blockIdx.y;
    if (threadIdx.x == 0) snv = g_nval[b];
    if (threadIdx.x < G_) svb[threadIdx.x] = g_vgtbox[b*G_ + threadIdx.x];
    __syncthreads();
    int nv = snv;

    int a = blockIdx.x * blockDim.x + threadIdx.x;
    int lane = threadIdx.x & 31;
    float softplus_obj = 0.f;
    bool fg = false;
    float4 box = make_float4(0.f, 0.f, 0.f, 0.f);
    float Bo = 0.f, to = 0.f, cx = 0.f, cy = 0.f, rs = 0.f;

    if (a < NA_) {
        int hw, W, HW; float st;
        anchor_map(a, hw, W, HW, st);
        const float* src = (a < 6400) ? out0 : (a < 8000) ? out1 : out2;
        const float* p = src + (size_t)b * 85 * HW + hw;

        float tx = p[0], ty = p[HW], tw = p[2*HW], th = p[3*HW];
        to = p[4*HW];
        int h = hw / W, w = hw - h * W;
        box = make_float4((tx + (float)w) * st, (ty + (float)h) * st,
                          __expf(tw) * st, __expf(th) * st);
        Bo = 1.f + __expf(-to);
        softplus_obj = fmaxf(to, 0.f) + __logf(1.f + __expf(-fabsf(to)));

        cx = ((float)w + 0.5f) * st;
        cy = ((float)h + 0.5f) * st;
        rs = 2.5f * st;
        for (int j = 0; j < nv; j++) {
            float4 gb = svb[j];
            bool ib = (cx > gb.x - 0.5f*gb.z) && (cx < gb.x + 0.5f*gb.z) &&
                      (cy > gb.y - 0.5f*gb.w) && (cy < gb.y + 0.5f*gb.w);
            bool ic = (fabsf(cx - gb.x) < rs) && (fabsf(cy - gb.y) < rs);
            fg |= (ib | ic);
        }
    }

    unsigned bal = __ballot_sync(0xffffffffu, fg);
    if (bal) {
        int leader = __ffs(bal) - 1;
        int base = 0;
        if (lane == leader) base = atomicAdd(&g_nfg[b], __popc(bal));
        base = __shfl_sync(0xffffffffu, base, leader);
        if (fg) {
            int f = base + __popc(bal & ((1u << lane) - 1));
            int bf = b * NA_ + f;
            g_flist[bf] = a;
            g_cbox[bf] = box;
            g_cgeo[bf] = make_float4(cx, cy, rs, 0.f);
            g_cBo [bf] = Bo;
            g_cobj[bf] = to;
        }
    }

    #pragma unroll
    for (int off = 16; off; off >>= 1)
        softplus_obj += __shfl_down_sync(0xffffffffu, softplus_obj, off);
    __shared__ float swsum[8];
    int wid = threadIdx.x >> 5;
    if (lane == 0) swsum[wid] = softplus_obj;
    __syncthreads();
    if (threadIdx.x == 0) {
        float t = 0.f;
        for (int i = 0; i < 8; i++) t += swsum[i];
        atomicAdd(&g_accb[b][1], (double)t);
    }
}

// ---------------- K3: dense per-fg-anchor stats (slot-compressed U planes) ----------------
__global__ void k_stats(const float* __restrict__ out0,
                        const float* __restrict__ out1,
                        const float* __restrict__ out2) {
    __shared__ int sslot[NC_];
    int b = blockIdx.y;
    if (threadIdx.x < NC_) sslot[threadIdx.x] = g_slotofcls[b * NC_ + threadIdx.x];
    __syncthreads();

    int f = blockIdx.x * blockDim.x + threadIdx.x;
    if (f >= g_nfg[b]) return;
    int bf = b * NA_ + f;
    int a = g_flist[bf];
    int hw, W, HW; float st;
    anchor_map(a, hw, W, HW, st);
    const float* src = (a < 6400) ? out0 : (a < 8000) ? out1 : out2;
    const float* p = src + ((size_t)b * 85 + 5) * HW + hw;
    float Bo = g_cBo[bf];

    float s = 0.f, splog = 0.f, xsum = 0.f;
    #pragma unroll 2
    for (int c = 0; c < NC_; c += 4) {
        float x0 = __ldg(&p[(c+0)*HW]);
        float x1 = __ldg(&p[(c+1)*HW]);
        float x2 = __ldg(&p[(c+2)*HW]);
        float x3 = __ldg(&p[(c+3)*HW]);
        float A0 = 1.f + __expf(-x0);
        float A1 = 1.f + __expf(-x1);
        float A2 = 1.f + __expf(-x2);
        float A3 = 1.f + __expf(-x3);
        float pv0 = fminf(fmaxf(rsqrtf(A0*Bo), 1e-7f), 1.f - 1e-6f);
        float pv1 = fminf(fmaxf(rsqrtf(A1*Bo), 1e-7f), 1.f - 1e-6f);
        float pv2 = fminf(fmaxf(rsqrtf(A2*Bo), 1e-7f), 1.f - 1e-6f);
        float pv3 = fminf(fmaxf(rsqrtf(A3*Bo), 1e-7f), 1.f - 1e-6f);
        s     += __logf(((1.f-pv0)*(1.f-pv1)) * ((1.f-pv2)*(1.f-pv3)));
        splog += __logf((A0*A1) * (A2*A3));
        xsum  += (x0 + x1) + (x2 + x3);
        int s0_ = sslot[c+0], s1_ = sslot[c+1], s2_ = sslot[c+2], s3_ = sslot[c+3];
        if (s0_ >= 0) g_U[(size_t)s0_*BNA_ + bf] = __logf((1.f-pv0)/pv0);
        if (s1_ >= 0) g_U[(size_t)s1_*BNA_ + bf] = __logf((1.f-pv1)/pv1);
        if (s2_ >= 0) g_U[(size_t)s2_*BNA_ + bf] = __logf((1.f-pv2)/pv2);
        if (s3_ >= 0) g_U[(size_t)s3_*BNA_ + bf] = __logf((1.f-pv3)/pv3);
    }
    g_csp[bf] = xsum + splog;
    ((float*)g_cgeo)[4*bf + 3] = s;
}

// ---------------- K4: cost + topk, block(128) per (b, valid j) ----------------
#define TT_ 128
__global__ void __launch_bounds__(TT_) k_costtopk() {
    int b = blockIdx.y, j = blockIdx.x;
    if (j >= g_nval[b]) return;
    int N = g_nfg[b];
    if (N == 0) return;

    float4 gb = g_vgtbox[b*G_ + j];
    int slot = g_slotofcls[b * NC_ + g_vgtcls[b*G_ + j]];
    float gl = gb.x - gb.z*0.5f, gr = gb.x + gb.z*0.5f;
    float gt_ = gb.y - gb.w*0.5f, gbm = gb.y + gb.w*0.5f;
    const float*  Up   = g_U + (size_t)slot * BNA_ + b * NA_;
    const float4* cbox = g_cbox + b * NA_;
    const float4* cgeo = g_cgeo + b * NA_;
    float* crow = g_cost + (size_t)(b * G_ + j) * NA_;

    int wid = threadIdx.x >> 5, lane = threadIdx.x & 31;

    float lc[10], li[10];
    #pragma unroll
    for (int i = 0; i < 10; i++) { lc[i] = 3.0e38f; li[i] = 0.f; }

    // unroll x2 for MLP
    int f = threadIdx.x;
    for (; f + TT_ < N; f += 2*TT_) {
        float4 bb0 = __ldg(&cbox[f]);
        float4 bb1 = __ldg(&cbox[f + TT_]);
        float4 ge0 = __ldg(&cgeo[f]);
        float4 ge1 = __ldg(&cgeo[f + TT_]);
        float  U0  = __ldg(&Up[f]);
        float  U1  = __ldg(&Up[f + TT_]);

        float iou0 = pair_iou(gb, bb0);
        float iou1 = pair_iou(gb, bb1);

        bool geom0 = (ge0.x > gl) && (ge0.x < gr) && (ge0.y > gt_) && (ge0.y < gbm)
                   && (fabsf(ge0.x - gb.x) < ge0.z) && (fabsf(ge0.y - gb.y) < ge0.z);
        bool geom1 = (ge1.x > gl) && (ge1.x < gr) && (ge1.y > gt_) && (ge1.y < gbm)
                   && (fabsf(ge1.x - gb.x) < ge1.z) && (fabsf(ge1.y - gb.y) < ge1.z);

        float c0 = U0 - ge0.w - 3.f * __logf(iou0 + 1e-8f) + (geom0 ? 0.f : 100000.f);
        float c1 = U1 - ge1.w - 3.f * __logf(iou1 + 1e-8f) + (geom1 ? 0.f : 100000.f);

        crow[f]       = c0;
        crow[f + TT_] = c1;
        ins_min10(lc, c0);
        ins_min10(lc, c1);
        ins_max10(li, iou0);
        ins_max10(li, iou1);
    }
    for (; f < N; f += TT_) {
        float4 bb = __ldg(&cbox[f]);
        float4 ge = __ldg(&cgeo[f]);
        float  U  = __ldg(&Up[f]);
        float iou = pair_iou(gb, bb);
        bool geom = (ge.x > gl) && (ge.x < gr) && (ge.y > gt_) && (ge.y < gbm)
                  && (fabsf(ge.x - gb.x) < ge.z) && (fabsf(ge.y - gb.y) < ge.z);
        float c = U - ge.w - 3.f * __logf(iou + 1e-8f) + (geom ? 0.f : 100000.f);
        crow[f] = c;
        ins_min10(lc, c);
        ins_max10(li, iou);
    }

    // level 1: per-warp merge -> 10 values each in shared (4 warps)
    __shared__ float swc[4*10], swi[4*10];
    for (int k = 0; k < 10; k++) {          // iou descending
        float bv = li[0]; int bl = lane;
        #pragma unroll
        for (int off = 16; off; off >>= 1) {
            float ov = __shfl_down_sync(0xffffffffu, bv, off);
            int   ol = __shfl_down_sync(0xffffffffu, bl, off);
            if (ov > bv || (ov == bv && ol < bl)) { bv = ov; bl = ol; }
        }
        bv = __shfl_sync(0xffffffffu, bv, 0);
        bl = __shfl_sync(0xffffffffu, bl, 0);
        if (lane == bl) {
            #pragma unroll
            for (int q = 0; q < 9; q++) li[q] = li[q+1];
            li[9] = -3.0e38f;
        }
        if (lane == 0) swi[wid*10 + k] = bv;
    }
    for (int k = 0; k < 10; k++) {          // cost ascending
        float bv = lc[0]; int bl = lane;
        #pragma unroll
        for (int off = 16; off; off >>= 1) {
            float ov = __shfl_down_sync(0xffffffffu, bv, off);
            int   ol = __shfl_down_sync(0xffffffffu, bl, off);
            if (ov < bv || (ov == bv && ol < bl)) { bv = ov; bl = ol; }
        }
        bv = __shfl_sync(0xffffffffu, bv, 0);
        bl = __shfl_sync(0xffffffffu, bl, 0);
        if (lane == bl) {
            #pragma unroll
            for (int q = 0; q < 9; q++) lc[q] = lc[q+1];
            lc[9] = 3.0e38f;
        }
        if (lane == 0) swc[wid*10 + k] = bv;
    }
    __syncthreads();

    // level 2: warp 0 merges 40 candidates
    if (wid != 0) return;
    #pragma unroll
    for (int i = 0; i < 10; i++) { lc[i] = 3.0e38f; li[i] = 0.f; }
    for (int i = lane; i < 40; i += 32) {
        ins_min10(lc, swc[i]);
        ins_max10(li, swi[i]);
    }

    float isum = 0.f;
    for (int k = 0; k < 10; k++) {
        float bv = li[0]; int bl = lane;
        #pragma unroll
        for (int off = 16; off; off >>= 1) {
            float ov = __shfl_down_sync(0xffffffffu, bv, off);
            int   ol = __shfl_down_sync(0xffffffffu, bl, off);
            if (ov > bv || (ov == bv && ol < bl)) { bv = ov; bl = ol; }
        }
        bv = __shfl_sync(0xffffffffu, bv, 0);
        bl = __shfl_sync(0xffffffffu, bl, 0);
        if (lane == bl) {
            #pragma unroll
            for (int q = 0; q < 9; q++) li[q] = li[q+1];
            li[9] = -3.0e38f;
        }
        isum += bv;
    }
    int dynk = (int)isum;
    if (dynk < 1) dynk = 1;
    if (dynk > 10) dynk = 10;
    if (dynk > N) dynk = N;

    float thr = 0.f;
    for (int k = 0; k < 10; k++) {
        float bv = lc[0]; int bl = lane;
        #pragma unroll
        for (int off = 16; off; off >>= 1) {
            float ov = __shfl_down_sync(0xffffffffu, bv, off);
            int   ol = __shfl_down_sync(0xffffffffu, bl, off);
            if (ov < bv || (ov == bv && ol < bl)) { bv = ov; bl = ol; }
        }
        bv = __shfl_sync(0xffffffffu, bv, 0);
        bl = __shfl_sync(0xffffffffu, bl, 0);
        if (lane == bl) {
            #pragma unroll
            for (int q = 0; q < 9; q++) lc[q] = lc[q+1];
            lc[9] = 3.0e38f;
        }
        if (k == dynk - 1) thr = bv;
    }
    if (lane == 0) g_thr[b*G_ + j] = thr;
}

// ---------------- K5: resolve (warp per fg anchor, grid-stride) ----------------
#define RW_ 8
#define RBLK_ 64
__global__ void k_resolve(const float* __restrict__ out0,
                          const float* __restrict__ out1,
                          const float* __restrict__ out2) {
    int b = blockIdx.y;
    int wid = threadIdx.x >> 5, lane = threadIdx.x & 31;
    int nfg = g_nfg[b];
    int nv  = g_nval[b];

    float liou = 0.f, lobj = 0.f, lcls = 0.f, lfg = 0.f;

    for (int f = blockIdx.x * RW_ + wid; f < nfg; f += RBLK_ * RW_) {
        int bf = b * NA_ + f;

        int j0 = lane, j1 = lane + 32;
        bool v0 = j0 < nv, v1 = j1 < nv;
        float c0 = v0 ? __ldg(&g_cost[(size_t)(b*G_ + j0) * NA_ + f]) : 3.4e38f;
        float c1 = v1 ? __ldg(&g_cost[(size_t)(b*G_ + j1) * NA_ + f]) : 3.4e38f;
        float t0 = v0 ? g_thr[b*G_ + j0] : 0.f;
        float t1 = v1 ? g_thr[b*G_ + j1] : 0.f;
        bool m0 = v0 && (c0 <= t0);
        bool m1 = v1 && (c1 <= t1);
        int count = __popc(__ballot_sync(0xffffffffu, m0))
                  + __popc(__ballot_sync(0xffffffffu, m1));

        float cmin = fminf(c0, c1);
        int   jmin = (c0 <= c1) ? j0 : j1;
        #pragma unroll
        for (int off = 16; off; off >>= 1) {
            float ov = __shfl_xor_sync(0xffffffffu, cmin, off);
            int   oj = __shfl_xor_sync(0xffffffffu, jmin, off);
            if (ov < cmin || (ov == cmin && oj < jmin)) { cmin = ov; jmin = oj; }
        }

        if (count > 1) {
            m0 = m0 && (j0 == jmin);
            m1 = m1 && (j1 == jmin);
        }
        unsigned fb0 = __ballot_sync(0xffffffffu, m0);
        unsigned fb1 = __ballot_sync(0xffffffffu, m1);
        bool fgfin = (fb0 | fb1) != 0u;

        if (fgfin) {
            int mj = fb0 ? (__ffs(fb0) - 1) : (32 + __ffs(fb1) - 1);

            // owner lane computes losses (match set is exactly one gt)
            if (lane == (mj & 31)) {
                float4 gbx = g_vgtbox[b*G_ + mj];
                float4 bb = g_cbox[bf];
                // piou: bit-identical recompute of costtopk's pairwise iou
                float piou = pair_iou(gbx, bb);

                // iou loss (clipped variant)
                float tlx = fmaxf(bb.x - bb.z*0.5f, gbx.x - gbx.z*0.5f);
                float tly = fmaxf(bb.y - bb.w*0.5f, gbx.y - gbx.w*0.5f);
                float brx = fminf(bb.x + bb.z*0.5f, gbx.x + gbx.z*0.5f);
                float bry = fminf(bb.y + bb.w*0.5f, gbx.y + gbx.w*0.5f);
                float en  = (tlx < brx && tly < bry) ? 1.f : 0.f;
                float inter = fmaxf(brx - tlx, 0.f) * fmaxf(bry - tly, 0.f) * en;
                float uni = bb.z*bb.w + gbx.z*gbx.w - inter + 1e-16f;
                float iou = inter / uni;
                liou += 1.f - iou * iou;
                lfg  += 1.f;
                lobj += -g_cobj[bf];   // softplus(obj) accumulated in decode

                int mcls = g_vgtcls[b*G_ + mj];
                int a = g_flist[bf];
                int hw, W, HW; float st;
                anchor_map(a, hw, W, HW, st);
                const float* src = (a < 6400) ? out0 : (a < 8000) ? out1 : out2;
                float xm = __ldg(&src[((size_t)b * 85 + 5 + mcls) * HW + hw]);
                lcls += g_csp[bf] - xm * piou;
            }
        }
    }

    #pragma unroll
    for (int off = 16; off; off >>= 1) {
        liou += __shfl_down_sync(0xffffffffu, liou, off);
        lobj += __shfl_down_sync(0xffffffffu, lobj, off);
        lcls += __shfl_down_sync(0xffffffffu, lcls, off);
        lfg  += __shfl_down_sync(0xffffffffu, lfg,  off);
    }
    __shared__ float s4[RW_][4];
    if (lane == 0) { s4[wid][0] = liou; s4[wid][1] = lobj; s4[wid][2] = lcls; s4[wid][3] = lfg; }
    __syncthreads();
    if (threadIdx.x == 0) {
        float a0 = 0.f, a1 = 0.f, a2 = 0.f, a3 = 0.f;
        for (int i = 0; i < RW_; i++) { a0 += s4[i][0]; a1 += s4[i][1]; a2 += s4[i][2]; a3 += s4[i][3]; }
        if (a0 != 0.f) atomicAdd(&g_accb[b][0], (double)a0);
        if (a1 != 0.f) atomicAdd(&g_accb[b][1], (double)a1);
        if (a2 != 0.f) atomicAdd(&g_accb[b][2], (double)a2);
        if (a3 != 0.f) atomicAdd(&g_accb[b][3], (double)a3);
    }
}

// ---------------- K6: finalize ----------------
__global__ void k_final(float* __restrict__ out) {
    if (threadIdx.x == 0) {
        double si = 0.0, so = 0.0, sc = 0.0, nf = 0.0;
        for (int b = 0; b < B_; b++) {
            si += g_accb[b][0]; so += g_accb[b][1];
            sc += g_accb[b][2]; nf += g_accb[b][3];
        }
        if (nf < 1.0) nf = 1.0;
        out[0] = (float)((5.0 * si + so + sc) / nf);
    }
}

// ---------------- launch ----------------
extern "C" void kernel_launch(void* const* d_in, const int* in_sizes, int n_in,
                              void* d_out, int out_size) {
    const float* out0   = (const float*)d_in[0];
    const float* out1   = (const float*)d_in[1];
    const float* out2   = (const float*)d_in[2];
    const float* labels = (const float*)d_in[3];
    float* out = (float*)d_out;

    k_gt<<<B_, 128>>>(labels);
    {
        dim3 g((NA_ + 255) / 256, B_);
        k_decode<<<g, 256>>>(out0, out1, out2);
    }
    {
        dim3 g((NA_ + 255) / 256, B_);
        k_stats<<<g, 256>>>(out0, out1, out2);
    }
    {
        dim3 g(G_, B_);
        k_costtopk<<<g, TT_>>>();
    }
    {
        dim3 g(RBLK_, B_);
        k_resolve<<<g, RW_*32>>>(out0, out1, out2);
    }
    k_final<<<1, 32>>>(out);
}